// round 1
// baseline (speedup 1.0000x reference)
#include <cuda_runtime.h>

#define HD 128
#define MAXN 100096
#define MAXE 1600000

// ---------------- device scratch (static, no allocation) ----------------
__device__ __align__(16) float g_bufA[MAXN * HD];   // GEMM output, pre-scaled by norm[src]
__device__ __align__(16) float g_bufB[MAXN * HD];   // aggregation output (layer activations)
__device__ int   g_counts[MAXN];
__device__ int   g_offsets[MAXN];
__device__ int   g_cursor[MAXN];
__device__ float g_norm[MAXN];
__device__ int   g_csr[MAXE];
__device__ int   g_bsums[128];

// ---------------- packed fp32x2 helpers (sm_100+) ----------------
__device__ __forceinline__ unsigned long long fma2(unsigned long long a,
                                                   unsigned long long b,
                                                   unsigned long long c) {
    unsigned long long d;
    asm("fma.rn.f32x2 %0, %1, %2, %3;" : "=l"(d) : "l"(a), "l"(b), "l"(c));
    return d;
}
__device__ __forceinline__ unsigned long long pack2(float x) {
    unsigned long long d;
    asm("mov.b64 %0, {%1, %1};" : "=l"(d) : "f"(x));
    return d;
}
__device__ __forceinline__ float2 unpack2(unsigned long long v) {
    float2 r;
    asm("mov.b64 {%0, %1}, %2;" : "=f"(r.x), "=f"(r.y) : "l"(v));
    return r;
}

// ---------------- CSR build ----------------
__global__ void zero_counts_kernel(int n) {
    int i = blockIdx.x * blockDim.x + threadIdx.x;
    if (i < n) g_counts[i] = 0;
}

__global__ void count_edges_kernel(const int* __restrict__ adj, int E_) {
    int e = blockIdx.x * blockDim.x + threadIdx.x;
    if (e < E_) atomicAdd(&g_counts[adj[E_ + e]], 1);
}

__global__ void scan_local_kernel(int n) {
    __shared__ int sm[1024];
    int tid = threadIdx.x;
    int i = blockIdx.x * 1024 + tid;
    int v = (i < n) ? g_counts[i] : 0;
    int x = v;
    sm[tid] = x;
    __syncthreads();
    #pragma unroll
    for (int off = 1; off < 1024; off <<= 1) {
        int y = (tid >= off) ? sm[tid - off] : 0;
        __syncthreads();
        x += y;
        sm[tid] = x;
        __syncthreads();
    }
    if (i < n) g_offsets[i] = x - v;            // exclusive
    if (tid == 1023) g_bsums[blockIdx.x] = x;   // block total
}

__global__ void scan_sums_kernel(int nb) {
    __shared__ int sm[128];
    int tid = threadIdx.x;
    int v = (tid < nb) ? g_bsums[tid] : 0;
    int x = v;
    sm[tid] = x;
    __syncthreads();
    #pragma unroll
    for (int off = 1; off < 128; off <<= 1) {
        int y = (tid >= off) ? sm[tid - off] : 0;
        __syncthreads();
        x += y;
        sm[tid] = x;
        __syncthreads();
    }
    if (tid < nb) g_bsums[tid] = x - v;         // exclusive
}

__global__ void finalize_offsets_kernel(int n) {
    int i = blockIdx.x * blockDim.x + threadIdx.x;
    if (i < n) {
        g_offsets[i] += g_bsums[i >> 10];
        g_cursor[i] = 0;
        int c = g_counts[i];
        g_norm[i] = (c > 0) ? rsqrtf((float)c) : 0.0f;
    }
}

__global__ void fill_csr_kernel(const int* __restrict__ adj, int E_) {
    int e = blockIdx.x * blockDim.x + threadIdx.x;
    if (e < E_) {
        int s = adj[e];
        int d = adj[E_ + e];
        int idx = g_offsets[d] + atomicAdd(&g_cursor[d], 1);
        g_csr[idx] = s;
    }
}

// ---------------- GEMM: C[r] = (A[r] @ W + b) * norm[r] ----------------
// block: 256 threads (16x16), tile 64 rows x 128 cols. W + A tile in smem (96KB dynamic).
// inner loop uses packed fma.rn.f32x2 (2x fp32 FMA rate).
__global__ void gemm_scale_kernel(const float* __restrict__ A,
                                  const float* __restrict__ W,
                                  const float* __restrict__ bias,
                                  float* __restrict__ C, int n) {
    extern __shared__ float smem[];
    float* Ws = smem;               // 128*128 floats
    float* As = smem + HD * HD;     // 64*128 floats
    int tid = threadIdx.x;
    int row0 = blockIdx.x * 64;

    // load W (16384 floats = 4096 float4)
    {
        const float4* W4 = (const float4*)W;
        float4* Ws4 = (float4*)Ws;
        #pragma unroll
        for (int i = 0; i < 16; i++) Ws4[tid + 256 * i] = W4[tid + 256 * i];
    }
    // load A tile (64 rows x 32 float4)
    {
        const float4* A4 = (const float4*)A;
        float4* As4 = (float4*)As;
        #pragma unroll
        for (int i = 0; i < 8; i++) {
            int idx = tid + 256 * i;
            int r = idx >> 5, c = idx & 31;
            int gr = row0 + r;
            As4[idx] = (gr < n) ? A4[gr * 32 + c] : make_float4(0.f, 0.f, 0.f, 0.f);
        }
    }
    __syncthreads();

    int tx = tid & 15, ty = tid >> 4;
    unsigned long long acc[4][4];
    #pragma unroll
    for (int p = 0; p < 4; p++)
        #pragma unroll
        for (int q = 0; q < 4; q++) acc[p][q] = 0ull;

    #pragma unroll 8
    for (int k = 0; k < HD; k++) {
        const unsigned long long* Wr = (const unsigned long long*)(Ws + k * HD);
        unsigned long long w0 = Wr[tx];
        unsigned long long w1 = Wr[tx + 16];
        unsigned long long w2 = Wr[tx + 32];
        unsigned long long w3 = Wr[tx + 48];
        #pragma unroll
        for (int p = 0; p < 4; p++) {
            unsigned long long a2 = pack2(As[(ty + 16 * p) * HD + k]);
            acc[p][0] = fma2(a2, w0, acc[p][0]);
            acc[p][1] = fma2(a2, w1, acc[p][1]);
            acc[p][2] = fma2(a2, w2, acc[p][2]);
            acc[p][3] = fma2(a2, w3, acc[p][3]);
        }
    }

    const float2* b2p = (const float2*)bias;
    float2* C2 = (float2*)C;
    #pragma unroll
    for (int p = 0; p < 4; p++) {
        int gr = row0 + ty + 16 * p;
        if (gr < n) {
            float nr = g_norm[gr];
            #pragma unroll
            for (int q = 0; q < 4; q++) {
                float2 v = unpack2(acc[p][q]);
                float2 bb = b2p[tx + 16 * q];
                C2[gr * 64 + tx + 16 * q] =
                    make_float2((v.x + bb.x) * nr, (v.y + bb.y) * nr);
            }
        }
    }
}

// ---------------- aggregation: Out[d] = relu(norm[d] * sum_{src in CSR(d)} Hs[src]) --
// one warp per dst node; lane l owns float4 chunk l of the 128-wide row.
__global__ void aggregate_kernel(const float* __restrict__ Hs,
                                 float* __restrict__ Out, int n) {
    int gw = (blockIdx.x * blockDim.x + threadIdx.x) >> 5;
    int lane = threadIdx.x & 31;
    if (gw >= n) return;
    int start = g_offsets[gw];
    int cnt = g_counts[gw];
    const float4* H4 = (const float4*)Hs;
    float ax = 0.f, ay = 0.f, az = 0.f, aw = 0.f;
    for (int base = 0; base < cnt; base += 32) {
        int rem = cnt - base;
        int e = 0;
        if (lane < rem) e = g_csr[start + base + lane];
        int m = rem < 32 ? rem : 32;
        for (int j = 0; j < m; j++) {
            int s = __shfl_sync(0xffffffffu, e, j);
            float4 v = __ldg(&H4[s * 32 + lane]);
            ax += v.x; ay += v.y; az += v.z; aw += v.w;
        }
    }
    float nr = g_norm[gw];
    float4 o = make_float4(fmaxf(ax * nr, 0.f), fmaxf(ay * nr, 0.f),
                           fmaxf(az * nr, 0.f), fmaxf(aw * nr, 0.f));
    ((float4*)Out)[gw * 32 + lane] = o;
}

// ---------------- pooling + MLP head (one block per graph) ----------------
__device__ __forceinline__ int lower_bound_dev(const int* a, int n, int key) {
    int lo = 0, hi = n;
    while (lo < hi) {
        int mid = (lo + hi) >> 1;
        if (a[mid] < key) lo = mid + 1; else hi = mid;
    }
    return lo;
}

__global__ void pool_head_kernel(const float* __restrict__ H,
                                 const int* __restrict__ gidx,
                                 const float* __restrict__ Wfc,
                                 const float* __restrict__ bfc,
                                 const float* __restrict__ Wout,
                                 const float* __restrict__ bout,
                                 float* __restrict__ out, int n) {
    __shared__ float gf[HD];
    __shared__ float red[HD];
    __shared__ int bounds[2];
    int g = blockIdx.x, t = threadIdx.x;
    if (t < 2) bounds[t] = lower_bound_dev(gidx, n, g + t);
    __syncthreads();
    int start = bounds[0], end = bounds[1];
    float s = 0.f;
    for (int i = start; i < end; i++) s += H[i * HD + t];
    gf[t] = s / fmaxf((float)(end - start), 1.0f);
    __syncthreads();
    float acc = bfc[t];
    #pragma unroll 8
    for (int k = 0; k < HD; k++) acc += gf[k] * Wfc[k * HD + t];
    red[t] = fmaxf(acc, 0.f) * Wout[t];
    __syncthreads();
    #pragma unroll
    for (int sft = 64; sft > 0; sft >>= 1) {
        if (t < sft) red[t] += red[t + sft];
        __syncthreads();
    }
    if (t == 0) out[g] = red[0] + bout[0];
}

// ---------------- launch ----------------
extern "C" void kernel_launch(void* const* d_in, const int* in_sizes, int n_in,
                              void* d_out, int out_size) {
    const float* node = (const float*)d_in[0];
    const int*   adj  = (const int*)d_in[1];
    const int*   gidx = (const int*)d_in[2];
    // d_in[3] = is_training (ignored, eval mode)
    const float* W1   = (const float*)d_in[4];
    const float* b1   = (const float*)d_in[5];
    const float* W2   = (const float*)d_in[6];
    const float* b2   = (const float*)d_in[7];
    const float* Wfc  = (const float*)d_in[8];
    const float* bfc  = (const float*)d_in[9];
    const float* Wout = (const float*)d_in[10];
    const float* bout = (const float*)d_in[11];

    int n  = in_sizes[2];          // N nodes
    int E_ = in_sizes[1] / 2;      // E edges
    int G_ = out_size;             // G graphs (OUT=1)

    float* bufA; float* bufB;
    cudaGetSymbolAddress((void**)&bufA, g_bufA);
    cudaGetSymbolAddress((void**)&bufB, g_bufB);

    const int gemm_smem = (HD * HD + 64 * HD) * (int)sizeof(float); // 96KB
    cudaFuncSetAttribute(gemm_scale_kernel,
                         cudaFuncAttributeMaxDynamicSharedMemorySize, gemm_smem);

    int nb = (n + 1023) / 1024;

    // CSR build (per-dst buckets) + norm
    zero_counts_kernel<<<(n + 255) / 256, 256>>>(n);
    count_edges_kernel<<<(E_ + 255) / 256, 256>>>(adj, E_);
    scan_local_kernel<<<nb, 1024>>>(n);
    scan_sums_kernel<<<1, 128>>>(nb);
    finalize_offsets_kernel<<<(n + 255) / 256, 256>>>(n);
    fill_csr_kernel<<<(E_ + 255) / 256, 256>>>(adj, E_);

    int gemm_blocks = (n + 63) / 64;
    int agg_blocks  = (n + 7) / 8;   // 8 warps / block, 1 warp per node

    // layer 1
    gemm_scale_kernel<<<gemm_blocks, 256, gemm_smem>>>(node, W1, b1, bufA, n);
    aggregate_kernel<<<agg_blocks, 256>>>(bufA, bufB, n);
    // layer 2
    gemm_scale_kernel<<<gemm_blocks, 256, gemm_smem>>>(bufB, W2, b2, bufA, n);
    aggregate_kernel<<<agg_blocks, 256>>>(bufA, bufB, n);
    // pool + head
    pool_head_kernel<<<G_, HD>>>(bufB, gidx, Wfc, bfc, Wout, bout,
                                 (float*)d_out, n);
}

// round 2
// speedup vs baseline: 1.1361x; 1.1361x over previous
#include <cuda_runtime.h>
#include <cuda_fp16.h>

#define HD 128
#define MAXN 100096
#define MAXE 1600000

// ---------------- device scratch (static, no allocation) ----------------
__device__ __align__(16) __half g_bufH[MAXN * HD];  // GEMM output (fp16, gathered by agg)
__device__ __align__(16) float  g_bufB[MAXN * HD];  // aggregation output (fp32 activations)
__device__ int   g_counts[MAXN];
__device__ int   g_offsets[MAXN];
__device__ int   g_cursor[MAXN];
__device__ float g_norm[MAXN];
__device__ int   g_csr[MAXE];
__device__ int   g_bsums[128];

// ---------------- packed fp32x2 helpers (sm_100+) ----------------
__device__ __forceinline__ unsigned long long fma2(unsigned long long a,
                                                   unsigned long long b,
                                                   unsigned long long c) {
    unsigned long long d;
    asm("fma.rn.f32x2 %0, %1, %2, %3;" : "=l"(d) : "l"(a), "l"(b), "l"(c));
    return d;
}
__device__ __forceinline__ unsigned long long pack2(float x) {
    unsigned long long d;
    asm("mov.b64 %0, {%1, %1};" : "=l"(d) : "f"(x));
    return d;
}
__device__ __forceinline__ float2 unpack2(unsigned long long v) {
    float2 r;
    asm("mov.b64 {%0, %1}, %2;" : "=f"(r.x), "=f"(r.y) : "l"(v));
    return r;
}

// ---------------- CSR build ----------------
__global__ void count_edges_kernel(const int* __restrict__ adj, int E_) {
    int e = blockIdx.x * blockDim.x + threadIdx.x;
    if (e < E_) atomicAdd(&g_counts[adj[E_ + e]], 1);
}

__global__ void scan_local_kernel(int n) {
    __shared__ int sm[1024];
    int tid = threadIdx.x;
    int i = blockIdx.x * 1024 + tid;
    int v = (i < n) ? g_counts[i] : 0;
    int x = v;
    sm[tid] = x;
    __syncthreads();
    #pragma unroll
    for (int off = 1; off < 1024; off <<= 1) {
        int y = (tid >= off) ? sm[tid - off] : 0;
        __syncthreads();
        x += y;
        sm[tid] = x;
        __syncthreads();
    }
    if (i < n) g_offsets[i] = x - v;            // exclusive
    if (tid == 1023) g_bsums[blockIdx.x] = x;   // block total
}

__global__ void scan_sums_kernel(int nb) {
    __shared__ int sm[128];
    int tid = threadIdx.x;
    int v = (tid < nb) ? g_bsums[tid] : 0;
    int x = v;
    sm[tid] = x;
    __syncthreads();
    #pragma unroll
    for (int off = 1; off < 128; off <<= 1) {
        int y = (tid >= off) ? sm[tid - off] : 0;
        __syncthreads();
        x += y;
        sm[tid] = x;
        __syncthreads();
    }
    if (tid < nb) g_bsums[tid] = x - v;         // exclusive
}

__global__ void finalize_offsets_kernel(int n) {
    int i = blockIdx.x * blockDim.x + threadIdx.x;
    if (i < n) {
        g_offsets[i] += g_bsums[i >> 10];
        g_cursor[i] = 0;
        int c = g_counts[i];
        g_norm[i] = (c > 0) ? rsqrtf((float)c) : 0.0f;
    }
}

__global__ void fill_csr_kernel(const int* __restrict__ adj, int E_) {
    int e = blockIdx.x * blockDim.x + threadIdx.x;
    if (e < E_) {
        int s = adj[e];
        int d = adj[E_ + e];
        int idx = g_offsets[d] + atomicAdd(&g_cursor[d], 1);
        g_csr[idx] = s;
    }
}

// ---------------- GEMM: C[r] = fp16( (A[r] @ W + b) * norm[r] ) ----------------
// block: 256 threads (16x16), tile 64 rows x 128 cols. W + A tile in smem (96KB dynamic).
// fp32 math via packed fma.rn.f32x2; fp16 only at the final store.
__global__ void gemm_scale_kernel(const float* __restrict__ A,
                                  const float* __restrict__ W,
                                  const float* __restrict__ bias,
                                  __half* __restrict__ C, int n) {
    extern __shared__ float smem[];
    float* Ws = smem;               // 128*128 floats
    float* As = smem + HD * HD;     // 64*128 floats
    int tid = threadIdx.x;
    int row0 = blockIdx.x * 64;

    // load W (16384 floats = 4096 float4)
    {
        const float4* W4 = (const float4*)W;
        float4* Ws4 = (float4*)Ws;
        #pragma unroll
        for (int i = 0; i < 16; i++) Ws4[tid + 256 * i] = W4[tid + 256 * i];
    }
    // load A tile (64 rows x 32 float4)
    {
        const float4* A4 = (const float4*)A;
        float4* As4 = (float4*)As;
        #pragma unroll
        for (int i = 0; i < 8; i++) {
            int idx = tid + 256 * i;
            int r = idx >> 5, c = idx & 31;
            int gr = row0 + r;
            As4[idx] = (gr < n) ? A4[gr * 32 + c] : make_float4(0.f, 0.f, 0.f, 0.f);
        }
    }
    __syncthreads();

    int tx = tid & 15, ty = tid >> 4;
    unsigned long long acc[4][4];
    #pragma unroll
    for (int p = 0; p < 4; p++)
        #pragma unroll
        for (int q = 0; q < 4; q++) acc[p][q] = 0ull;

    #pragma unroll 8
    for (int k = 0; k < HD; k++) {
        const unsigned long long* Wr = (const unsigned long long*)(Ws + k * HD);
        unsigned long long w0 = Wr[tx];
        unsigned long long w1 = Wr[tx + 16];
        unsigned long long w2 = Wr[tx + 32];
        unsigned long long w3 = Wr[tx + 48];
        #pragma unroll
        for (int p = 0; p < 4; p++) {
            unsigned long long a2 = pack2(As[(ty + 16 * p) * HD + k]);
            acc[p][0] = fma2(a2, w0, acc[p][0]);
            acc[p][1] = fma2(a2, w1, acc[p][1]);
            acc[p][2] = fma2(a2, w2, acc[p][2]);
            acc[p][3] = fma2(a2, w3, acc[p][3]);
        }
    }

    const float2* b2p = (const float2*)bias;
    __half2* C2 = (__half2*)C;
    #pragma unroll
    for (int p = 0; p < 4; p++) {
        int gr = row0 + ty + 16 * p;
        if (gr < n) {
            float nr = g_norm[gr];
            #pragma unroll
            for (int q = 0; q < 4; q++) {
                float2 v = unpack2(acc[p][q]);
                float2 bb = b2p[tx + 16 * q];
                float2 o = make_float2((v.x + bb.x) * nr, (v.y + bb.y) * nr);
                C2[gr * 64 + tx + 16 * q] = __float22half2_rn(o);
            }
        }
    }
}

// ---- aggregation: Out[d] = relu(norm[d] * sum_{src in CSR(d)} Hs[src]) ----
// one warp per dst node; lane l owns 4 halves (8B) of the 256B fp16 row,
// accumulates in fp32, writes a float4 of the fp32 output row.
__global__ void aggregate_kernel(const __half* __restrict__ Hs,
                                 float* __restrict__ Out, int n) {
    int gw = (blockIdx.x * blockDim.x + threadIdx.x) >> 5;
    int lane = threadIdx.x & 31;
    if (gw >= n) return;
    int start = g_offsets[gw];
    int cnt = g_counts[gw];
    const uint2* H2 = (const uint2*)Hs;   // row stride = 32 uint2 (256B)
    float ax = 0.f, ay = 0.f, az = 0.f, aw = 0.f;
    for (int base = 0; base < cnt; base += 32) {
        int rem = cnt - base;
        int e = 0;
        if (lane < rem) e = g_csr[start + base + lane];
        int m = rem < 32 ? rem : 32;
        for (int j = 0; j < m; j++) {
            int s = __shfl_sync(0xffffffffu, e, j);
            uint2 v = __ldg(&H2[s * 32 + lane]);
            __half2 h0 = *(__half2*)&v.x;
            __half2 h1 = *(__half2*)&v.y;
            float2 f0 = __half22float2(h0);
            float2 f1 = __half22float2(h1);
            ax += f0.x; ay += f0.y; az += f1.x; aw += f1.y;
        }
    }
    float nr = g_norm[gw];
    float4 o = make_float4(fmaxf(ax * nr, 0.f), fmaxf(ay * nr, 0.f),
                           fmaxf(az * nr, 0.f), fmaxf(aw * nr, 0.f));
    ((float4*)Out)[gw * 32 + lane] = o;
}

// ---------------- pooling + MLP head (one block per graph) ----------------
__device__ __forceinline__ int lower_bound_dev(const int* a, int n, int key) {
    int lo = 0, hi = n;
    while (lo < hi) {
        int mid = (lo + hi) >> 1;
        if (a[mid] < key) lo = mid + 1; else hi = mid;
    }
    return lo;
}

__global__ void pool_head_kernel(const float* __restrict__ H,
                                 const int* __restrict__ gidx,
                                 const float* __restrict__ Wfc,
                                 const float* __restrict__ bfc,
                                 const float* __restrict__ Wout,
                                 const float* __restrict__ bout,
                                 float* __restrict__ out, int n) {
    __shared__ float gf[HD];
    __shared__ float red[HD];
    __shared__ int bounds[2];
    int g = blockIdx.x, t = threadIdx.x;
    if (t < 2) bounds[t] = lower_bound_dev(gidx, n, g + t);
    __syncthreads();
    int start = bounds[0], end = bounds[1];
    float s = 0.f;
    for (int i = start; i < end; i++) s += H[i * HD + t];
    gf[t] = s / fmaxf((float)(end - start), 1.0f);
    __syncthreads();
    float acc = bfc[t];
    #pragma unroll 8
    for (int k = 0; k < HD; k++) acc += gf[k] * Wfc[k * HD + t];
    red[t] = fmaxf(acc, 0.f) * Wout[t];
    __syncthreads();
    #pragma unroll
    for (int sft = 64; sft > 0; sft >>= 1) {
        if (t < sft) red[t] += red[t + sft];
        __syncthreads();
    }
    if (t == 0) out[g] = red[0] + bout[0];
}

// ---------------- launch ----------------
extern "C" void kernel_launch(void* const* d_in, const int* in_sizes, int n_in,
                              void* d_out, int out_size) {
    const float* node = (const float*)d_in[0];
    const int*   adj  = (const int*)d_in[1];
    const int*   gidx = (const int*)d_in[2];
    // d_in[3] = is_training (ignored, eval mode)
    const float* W1   = (const float*)d_in[4];
    const float* b1   = (const float*)d_in[5];
    const float* W2   = (const float*)d_in[6];
    const float* b2   = (const float*)d_in[7];
    const float* Wfc  = (const float*)d_in[8];
    const float* bfc  = (const float*)d_in[9];
    const float* Wout = (const float*)d_in[10];
    const float* bout = (const float*)d_in[11];

    int n  = in_sizes[2];          // N nodes
    int E_ = in_sizes[1] / 2;      // E edges
    int G_ = out_size;             // G graphs (OUT=1)

    __half* bufH; float* bufB; int* countsPtr;
    cudaGetSymbolAddress((void**)&bufH, g_bufH);
    cudaGetSymbolAddress((void**)&bufB, g_bufB);
    cudaGetSymbolAddress((void**)&countsPtr, g_counts);

    const int gemm_smem = (HD * HD + 64 * HD) * (int)sizeof(float); // 96KB
    cudaFuncSetAttribute(gemm_scale_kernel,
                         cudaFuncAttributeMaxDynamicSharedMemorySize, gemm_smem);

    int nb = (n + 1023) / 1024;

    // CSR build (per-dst buckets) + norm
    cudaMemsetAsync(countsPtr, 0, (size_t)n * sizeof(int));
    count_edges_kernel<<<(E_ + 255) / 256, 256>>>(adj, E_);
    scan_local_kernel<<<nb, 1024>>>(n);
    scan_sums_kernel<<<1, 128>>>(nb);
    finalize_offsets_kernel<<<(n + 255) / 256, 256>>>(n);
    fill_csr_kernel<<<(E_ + 255) / 256, 256>>>(adj, E_);

    int gemm_blocks = (n + 63) / 64;
    int agg_blocks  = (n + 7) / 8;   // 8 warps / block, 1 warp per node

    // layer 1
    gemm_scale_kernel<<<gemm_blocks, 256, gemm_smem>>>(node, W1, b1, bufH, n);
    aggregate_kernel<<<agg_blocks, 256>>>(bufH, bufB, n);
    // layer 2
    gemm_scale_kernel<<<gemm_blocks, 256, gemm_smem>>>(bufB, W2, b2, bufH, n);
    aggregate_kernel<<<agg_blocks, 256>>>(bufH, bufB, n);
    // pool + head
    pool_head_kernel<<<G_, HD>>>(bufB, gidx, Wfc, bfc, Wout, bout,
                                 (float*)d_out, n);
}

// round 3
// speedup vs baseline: 1.8152x; 1.5977x over previous
#include <cuda_runtime.h>
#include <cuda_fp16.h>
#include <mma.h>
using namespace nvcuda;

#define HD 128
#define MAXN 100096
#define MAXE 1600000
#define SK 136   // smem stride in halves (padded)

// ---------------- device scratch (static, no allocation) ----------------
__device__ __align__(16) __half g_bufH[MAXN * HD];  // GEMM output (fp16, gathered by agg)
__device__ __align__(16) __half g_bufB[MAXN * HD];  // aggregation output (fp16 activations)
__device__ int   g_counts[MAXN];
__device__ int   g_offsets[MAXN];
__device__ int   g_cursor[MAXN];
__device__ float g_norm[MAXN];
__device__ int   g_csr[MAXE];
__device__ int   g_bsums[128];

// ---------------- CSR build ----------------
__global__ void count_edges_kernel(const int* __restrict__ adj, int E_) {
    int e = blockIdx.x * blockDim.x + threadIdx.x;
    if (e < E_) atomicAdd(&g_counts[adj[E_ + e]], 1);
}

__global__ void scan_local_kernel(int n) {
    __shared__ int sm[1024];
    int tid = threadIdx.x;
    int i = blockIdx.x * 1024 + tid;
    int v = (i < n) ? g_counts[i] : 0;
    int x = v;
    sm[tid] = x;
    __syncthreads();
    #pragma unroll
    for (int off = 1; off < 1024; off <<= 1) {
        int y = (tid >= off) ? sm[tid - off] : 0;
        __syncthreads();
        x += y;
        sm[tid] = x;
        __syncthreads();
    }
    if (i < n) g_offsets[i] = x - v;            // exclusive
    if (tid == 1023) g_bsums[blockIdx.x] = x;   // block total
}

__global__ void scan_sums_kernel(int nb) {
    __shared__ int sm[128];
    int tid = threadIdx.x;
    int v = (tid < nb) ? g_bsums[tid] : 0;
    int x = v;
    sm[tid] = x;
    __syncthreads();
    #pragma unroll
    for (int off = 1; off < 128; off <<= 1) {
        int y = (tid >= off) ? sm[tid - off] : 0;
        __syncthreads();
        x += y;
        sm[tid] = x;
        __syncthreads();
    }
    if (tid < nb) g_bsums[tid] = x - v;         // exclusive
}

__global__ void finalize_offsets_kernel(int n) {
    int i = blockIdx.x * blockDim.x + threadIdx.x;
    if (i < n) {
        g_offsets[i] += g_bsums[i >> 10];
        g_cursor[i] = 0;
        int c = g_counts[i];
        g_norm[i] = (c > 0) ? rsqrtf((float)c) : 0.0f;
    }
}

__global__ void fill_csr_kernel(const int* __restrict__ adj, int E_) {
    int e = blockIdx.x * blockDim.x + threadIdx.x;
    if (e < E_) {
        int s = adj[e];
        int d = adj[E_ + e];
        int idx = g_offsets[d] + atomicAdd(&g_cursor[d], 1);
        g_csr[idx] = s;
    }
}

// ---------------- tensor-core GEMM ----------------
// C[r] = fp16( (A[r] @ W + b) * norm[r] ),   A: [n,128] (fp32 or fp16), W: [128,128] fp32
// 256 threads / block, 128-row tile, K=128 resident. HMMA fp16 in / fp32 accum.
template<bool AHALF>
__global__ void gemm_mma_kernel(const void* __restrict__ Ain,
                                const float* __restrict__ W,
                                const float* __restrict__ bias,
                                __half* __restrict__ C, int n) {
    extern __shared__ char smem_raw[];
    __half* As = (__half*)smem_raw;           // 128 x SK halves
    __half* Ws = As + 128 * SK;               // 128 x SK halves
    float* stage = (float*)smem_raw;          // reused after mma loop
    int tid = threadIdx.x;
    int row0 = blockIdx.x * 128;

    // W fp32 -> fp16 smem
    {
        const float4* W4 = (const float4*)W;
        #pragma unroll
        for (int i = tid; i < 128 * 32; i += 256) {
            int r = i >> 5, c4 = i & 31;
            float4 v = W4[i];
            __half2* d = (__half2*)(Ws + r * SK + c4 * 4);
            d[0] = __floats2half2_rn(v.x, v.y);
            d[1] = __floats2half2_rn(v.z, v.w);
        }
    }
    // A tile -> fp16 smem
    if (AHALF) {
        const uint4* A4 = (const uint4*)Ain;   // 8 halves per uint4, 16 per row
        #pragma unroll
        for (int i = tid; i < 128 * 16; i += 256) {
            int r = i >> 4, c8 = i & 15;
            int gr = row0 + r;
            uint4 v = (gr < n) ? A4[gr * 16 + c8] : make_uint4(0, 0, 0, 0);
            *(uint4*)(As + r * SK + c8 * 8) = v;
        }
    } else {
        const float4* A4 = (const float4*)Ain;
        #pragma unroll
        for (int i = tid; i < 128 * 32; i += 256) {
            int r = i >> 5, c4 = i & 31;
            int gr = row0 + r;
            float4 v = (gr < n) ? A4[gr * 32 + c4] : make_float4(0.f, 0.f, 0.f, 0.f);
            __half2* d = (__half2*)(As + r * SK + c4 * 4);
            d[0] = __floats2half2_rn(v.x, v.y);
            d[1] = __floats2half2_rn(v.z, v.w);
        }
    }
    __syncthreads();

    int w = tid >> 5;
    int lane = tid & 31;
    int wm = (w >> 1) * 32;     // warp row base  (4 row groups of 32)
    int wn = (w & 1) * 64;      // warp col base  (2 col groups of 64)

    wmma::fragment<wmma::accumulator, 16, 16, 16, float> acc[2][4];
    #pragma unroll
    for (int p = 0; p < 2; p++)
        #pragma unroll
        for (int q = 0; q < 4; q++) wmma::fill_fragment(acc[p][q], 0.0f);

    #pragma unroll
    for (int k = 0; k < 128; k += 16) {
        wmma::fragment<wmma::matrix_a, 16, 16, 16, __half, wmma::row_major> af[2];
        wmma::fragment<wmma::matrix_b, 16, 16, 16, __half, wmma::row_major> bf[4];
        #pragma unroll
        for (int p = 0; p < 2; p++)
            wmma::load_matrix_sync(af[p], As + (wm + 16 * p) * SK + k, SK);
        #pragma unroll
        for (int q = 0; q < 4; q++)
            wmma::load_matrix_sync(bf[q], Ws + k * SK + wn + 16 * q, SK);
        #pragma unroll
        for (int p = 0; p < 2; p++)
            #pragma unroll
            for (int q = 0; q < 4; q++)
                wmma::mma_sync(acc[p][q], af[p], bf[q], acc[p][q]);
    }
    __syncthreads();   // all warps done reading As/Ws before staging overwrites

    // stage this warp's 32x64 fp32 result (ld = 72 to avoid conflicts)
    float* st = stage + w * (32 * 72);
    #pragma unroll
    for (int p = 0; p < 2; p++)
        #pragma unroll
        for (int q = 0; q < 4; q++)
            wmma::store_matrix_sync(st + 16 * p * 72 + 16 * q, acc[p][q], 72,
                                    wmma::mem_row_major);
    __syncwarp();

    // epilogue: (v + bias) * norm[row] -> fp16
    float2 bb = ((const float2*)bias)[(wn >> 1) + lane];   // cols wn+2*lane, wn+2*lane+1
    __half2* C2 = (__half2*)C;                              // row stride 64 half2
    #pragma unroll
    for (int r = 0; r < 32; r++) {
        int gr = row0 + wm + r;
        if (gr < n) {
            float nr = g_norm[gr];
            float2 v = *(float2*)(st + r * 72 + lane * 2);
            C2[gr * 64 + (wn >> 1) + lane] =
                __floats2half2_rn((v.x + bb.x) * nr, (v.y + bb.y) * nr);
        }
    }
}

// ---- aggregation: Out[d] = fp16( relu(norm[d] * sum_{src in CSR(d)} Hs[src]) ) ----
// one warp per dst node; lane l owns 4 halves (8B) of the 256B fp16 row; fp32 accum.
__global__ void aggregate_kernel(const __half* __restrict__ Hs,
                                 __half* __restrict__ Out, int n) {
    int gw = (blockIdx.x * blockDim.x + threadIdx.x) >> 5;
    int lane = threadIdx.x & 31;
    if (gw >= n) return;
    int start = g_offsets[gw];
    int cnt = g_counts[gw];
    const uint2* H2 = (const uint2*)Hs;   // row stride = 32 uint2 (256B)
    float ax = 0.f, ay = 0.f, az = 0.f, aw = 0.f;
    for (int base = 0; base < cnt; base += 32) {
        int rem = cnt - base;
        int e = 0;
        if (lane < rem) e = g_csr[start + base + lane];
        int m = rem < 32 ? rem : 32;
        for (int j = 0; j < m; j++) {
            int s = __shfl_sync(0xffffffffu, e, j);
            uint2 v = __ldg(&H2[s * 32 + lane]);
            float2 f0 = __half22float2(*(__half2*)&v.x);
            float2 f1 = __half22float2(*(__half2*)&v.y);
            ax += f0.x; ay += f0.y; az += f1.x; aw += f1.y;
        }
    }
    float nr = g_norm[gw];
    __half2 o0 = __floats2half2_rn(fmaxf(ax * nr, 0.f), fmaxf(ay * nr, 0.f));
    __half2 o1 = __floats2half2_rn(fmaxf(az * nr, 0.f), fmaxf(aw * nr, 0.f));
    uint2 o;
    o.x = *(unsigned*)&o0;
    o.y = *(unsigned*)&o1;
    ((uint2*)Out)[gw * 32 + lane] = o;
}

// ---------------- pooling + MLP head (one block per graph) ----------------
__device__ __forceinline__ int lower_bound_dev(const int* a, int n, int key) {
    int lo = 0, hi = n;
    while (lo < hi) {
        int mid = (lo + hi) >> 1;
        if (a[mid] < key) lo = mid + 1; else hi = mid;
    }
    return lo;
}

__global__ void pool_head_kernel(const __half* __restrict__ H,
                                 const int* __restrict__ gidx,
                                 const float* __restrict__ Wfc,
                                 const float* __restrict__ bfc,
                                 const float* __restrict__ Wout,
                                 const float* __restrict__ bout,
                                 float* __restrict__ out, int n) {
    __shared__ float gf[HD];
    __shared__ float red[HD];
    __shared__ int bounds[2];
    int g = blockIdx.x, t = threadIdx.x;
    if (t < 2) bounds[t] = lower_bound_dev(gidx, n, g + t);
    __syncthreads();
    int start = bounds[0], end = bounds[1];
    float s = 0.f;
    for (int i = start; i < end; i++) s += __half2float(H[i * HD + t]);
    gf[t] = s / fmaxf((float)(end - start), 1.0f);
    __syncthreads();
    float acc = bfc[t];
    #pragma unroll 8
    for (int k = 0; k < HD; k++) acc += gf[k] * Wfc[k * HD + t];
    red[t] = fmaxf(acc, 0.f) * Wout[t];
    __syncthreads();
    #pragma unroll
    for (int sft = 64; sft > 0; sft >>= 1) {
        if (t < sft) red[t] += red[t + sft];
        __syncthreads();
    }
    if (t == 0) out[g] = red[0] + bout[0];
}

// ---------------- launch ----------------
extern "C" void kernel_launch(void* const* d_in, const int* in_sizes, int n_in,
                              void* d_out, int out_size) {
    const float* node = (const float*)d_in[0];
    const int*   adj  = (const int*)d_in[1];
    const int*   gidx = (const int*)d_in[2];
    // d_in[3] = is_training (ignored, eval mode)
    const float* W1   = (const float*)d_in[4];
    const float* b1   = (const float*)d_in[5];
    const float* W2   = (const float*)d_in[6];
    const float* b2   = (const float*)d_in[7];
    const float* Wfc  = (const float*)d_in[8];
    const float* bfc  = (const float*)d_in[9];
    const float* Wout = (const float*)d_in[10];
    const float* bout = (const float*)d_in[11];

    int n  = in_sizes[2];          // N nodes
    int E_ = in_sizes[1] / 2;      // E edges
    int G_ = out_size;             // G graphs (OUT=1)

    __half* bufH; __half* bufB; int* countsPtr;
    cudaGetSymbolAddress((void**)&bufH, g_bufH);
    cudaGetSymbolAddress((void**)&bufB, g_bufB);
    cudaGetSymbolAddress((void**)&countsPtr, g_counts);

    // smem: max(two 128xSK half tiles, 8 warps * 32*72 floats staging)
    const int gemm_smem = (2 * 128 * SK * 2 > 8 * 32 * 72 * 4)
                              ? 2 * 128 * SK * 2 : 8 * 32 * 72 * 4;
    cudaFuncSetAttribute(gemm_mma_kernel<false>,
                         cudaFuncAttributeMaxDynamicSharedMemorySize, gemm_smem);
    cudaFuncSetAttribute(gemm_mma_kernel<true>,
                         cudaFuncAttributeMaxDynamicSharedMemorySize, gemm_smem);

    int nb = (n + 1023) / 1024;

    // CSR build (per-dst buckets) + norm
    cudaMemsetAsync(countsPtr, 0, (size_t)n * sizeof(int));
    count_edges_kernel<<<(E_ + 255) / 256, 256>>>(adj, E_);
    scan_local_kernel<<<nb, 1024>>>(n);
    scan_sums_kernel<<<1, 128>>>(nb);
    finalize_offsets_kernel<<<(n + 255) / 256, 256>>>(n);
    fill_csr_kernel<<<(E_ + 255) / 256, 256>>>(adj, E_);

    int gemm_blocks = (n + 127) / 128;
    int agg_blocks  = (n + 7) / 8;   // 8 warps / block, 1 warp per node

    // layer 1
    gemm_mma_kernel<false><<<gemm_blocks, 256, gemm_smem>>>(node, W1, b1, bufH, n);
    aggregate_kernel<<<agg_blocks, 256>>>(bufH, bufB, n);
    // layer 2
    gemm_mma_kernel<true><<<gemm_blocks, 256, gemm_smem>>>(bufB, W2, b2, bufH, n);
    aggregate_kernel<<<agg_blocks, 256>>>(bufH, bufB, n);
    // pool + head
    pool_head_kernel<<<G_, HD>>>(bufB, gidx, Wfc, bfc, Wout, bout,
                                 (float*)d_out, n);
}